// round 5
// baseline (speedup 1.0000x reference)
#include <cuda_runtime.h>

namespace {
constexpr int NTHREADS = 256;
constexpr int TILE   = 30;             // atoms per tile before padding
constexpr int PW     = 34;             // padded tile width (even; PW*d mod 32 conflict-free)
constexpr int HPW    = PW / 2;         // float2 stride
constexpr int NCOEF  = 316;            // 32*1 + 24*3 + 20*5 + 16*7
constexpr int NPAIR  = 1174;           // 528 + 300 + 210 + 136
constexpr int NRAD   = 64;
constexpr int NSP    = 4;
constexpr int NFEAT  = NPAIR + NRAD + 1;               // 1239
constexpr int NSLOTS = (NFEAT + NTHREADS - 1) / NTHREADS;  // 5
constexpr int SMAX   = 256;
constexpr int ASPLIT = 4;
constexpr int NCOLS  = NSP * NFEAT;    // 4956
}

__device__ int   g_start[SMAX + 1];
__device__ float g_part[ASPLIT][SMAX * NCOLS];   // ~20.3 MB scratch

// structure_index is sorted: g_start[s] = first atom of structure s.
__global__ void bounds_kernel(const int* __restrict__ sidx, int n_atoms, int S) {
    int i = blockIdx.x * blockDim.x + threadIdx.x;
    if (i >= n_atoms) return;
    int s  = sidx[i];
    int sp = (i == 0) ? -1 : sidx[i - 1];
    for (int t = sp + 1; t <= s && t <= SMAX; ++t) g_start[t] = i;
    if (i == n_atoms - 1)
        for (int t = s + 1; t <= S && t <= SMAX; ++t) g_start[t] = n_atoms;
}

// Pair invariant over species runs: atoms are pre-sorted by species in the tile,
// runs are even-length (zero-padded), so we FFMA straight into per-species accs.
template<int D>
__device__ __forceinline__ void accum_pairs(const float2* __restrict__ p1,
                                            const float2* __restrict__ p2,
                                            const int* __restrict__ rbeg,
                                            const int* __restrict__ rendp,
                                            float (&acc)[NSP]) {
#pragma unroll
    for (int sp = 0; sp < NSP; ++sp) {
        float ax = 0.f, ay = 0.f;
        const int h0 = rbeg[sp] >> 1, h1 = rendp[sp] >> 1;
        for (int h = h0; h < h1; ++h) {
#pragma unroll
            for (int j = 0; j < D; ++j) {
                float2 x = p1[j * HPW + h];
                float2 y = p2[(D - 1 - j) * HPW + h];
                if (j & 1) { ax = fmaf(-x.x, y.x, ax); ay = fmaf(-x.y, y.y, ay); }
                else       { ax = fmaf( x.x, y.x, ax); ay = fmaf( x.y, y.y, ay); }
            }
        }
        acc[sp] += ax + ay;
    }
}

__global__ __launch_bounds__(NTHREADS, 4)
void le_ace_kernel(const float* __restrict__ comp,
                   const float* __restrict__ radial,
                   const float* __restrict__ sph0,
                   const float* __restrict__ sph1,
                   const float* __restrict__ sph2,
                   const float* __restrict__ sph3,
                   const int* __restrict__ species,
                   int n_atoms, int S) {
    __shared__ __align__(16) float tileS[NCOEF * PW];   // 42976 B
    __shared__ int order[PW];
    __shared__ int cnt[NSP], rbeg[NSP], rendp[NSP], rcnt[NSP];

    const int tid  = threadIdx.x;
    const int lane = tid & 31;
    const int wid  = tid >> 5;
    const int s    = blockIdx.x;
    const int a    = blockIdx.y;

    // ---- per-thread feature-slot metadata (registers only) ----
    // sdv: 1/3/5/7 = pair D; 0 = radial (sc1 = radial col); -1 = comp; -2 = inactive
    int   sc1[NSLOTS], sc2[NSLOTS], sdv[NSLOTS];
    float ssc[NSLOTS];
    float facc[NSLOTS][NSP];
#pragma unroll
    for (int k = 0; k < NSLOTS; ++k) {
        int f = tid + k * NTHREADS;
        sc1[k] = 0; sc2[k] = 0; sdv[k] = -2; ssc[k] = 1.f;
#pragma unroll
        for (int sp = 0; sp < NSP; ++sp) facc[k][sp] = 0.f;
        if (f < NPAIR) {
            int l, q, base, coff;
            if (f < 528)       { l = 0; q = 32; base = 0;    coff = 0;   }
            else if (f < 828)  { l = 1; q = 24; base = 528;  coff = 32;  }
            else if (f < 1038) { l = 2; q = 20; base = 828;  coff = 104; }
            else               { l = 3; q = 16; base = 1038; coff = 204; }
            int rem = f - base, i1 = 0;
            while (rem >= q - i1) { rem -= q - i1; ++i1; }   // triangular inversion
            int i2 = i1 + rem;
            int d  = 2 * l + 1;
            sc1[k] = coff + i1 * d;
            sc2[k] = coff + i2 * d;
            sdv[k] = d;
            const float invsq[4] = {1.0f, 0.5773502691896258f,
                                    0.4472135954999579f, 0.3779644730092272f};
            ssc[k] = invsq[l] * ((i1 == i2) ? 1.0f : 1.4142135623730951f);
        } else if (f < NPAIR + NRAD) {
            sdv[k] = 0; sc1[k] = f - NPAIR;
        } else if (f == NPAIR + NRAD) {
            sdv[k] = -1;
        }
    }

    const int a0    = g_start[s];
    const int a1    = g_start[s + 1];
    const int len   = a1 - a0;
    const int chunk = (len + ASPLIT - 1) / ASPLIT;
    const int beg   = a0 + a * chunk;
    const int end   = min(beg + chunk, a1);

    for (int base = beg; base < end; base += TILE) {
        const int nt = min(TILE, end - base);
        __syncthreads();                    // previous tile fully consumed
        if (tid < NSP) cnt[tid] = 0;
        if (tid < PW)  order[tid] = -1;
        __syncthreads();
        int mysp = 0, myrank = 0;
        const bool active = (tid < nt);
        if (active) { mysp = species[base + tid]; myrank = atomicAdd(&cnt[mysp], 1); }
        __syncthreads();
        if (tid == 0) {
            int p = 0;
#pragma unroll
            for (int sp = 0; sp < NSP; ++sp) {
                rbeg[sp] = p; rcnt[sp] = cnt[sp];
                p += (cnt[sp] + 1) & ~1;    // pad run to even
                rendp[sp] = p;
            }
        }
        __syncthreads();
        if (active) order[rbeg[mysp] + myrank] = base + tid;
        __syncthreads();

        // ---- stage species-sorted coefficient tile (pads -> 0) ----
        const int o0 = order[lane];
        const int o1 = (lane < PW - 32) ? order[32 + lane] : -1;
        for (int c = wid; c < NCOEF; c += 8) {
            const float* p; int r;
            if (c < 32)       { p = sph0; r = c;       }
            else if (c < 104) { p = sph1; r = c - 32;  }
            else if (c < 204) { p = sph2; r = c - 104; }
            else              { p = sph3; r = c - 204; }
            tileS[c * PW + lane] = (o0 >= 0) ? p[(long)r * n_atoms + o0] : 0.f;
            if (lane < PW - 32)
                tileS[c * PW + 32 + lane] = (o1 >= 0) ? p[(long)r * n_atoms + o1] : 0.f;
        }
        __syncthreads();

        // ---- accumulate ----
#pragma unroll
        for (int k = 0; k < NSLOTS; ++k) {
            const int d = sdv[k];
            if (d > 0) {
                const float2* p1 = (const float2*)(tileS + sc1[k] * PW);
                const float2* p2 = (const float2*)(tileS + sc2[k] * PW);
                switch (d) {
                    case 1:  accum_pairs<1>(p1, p2, rbeg, rendp, facc[k]); break;
                    case 3:  accum_pairs<3>(p1, p2, rbeg, rendp, facc[k]); break;
                    case 5:  accum_pairs<5>(p1, p2, rbeg, rendp, facc[k]); break;
                    default: accum_pairs<7>(p1, p2, rbeg, rendp, facc[k]); break;
                }
            } else if (d == 0) {
                const int j = sc1[k];
#pragma unroll
                for (int sp = 0; sp < NSP; ++sp) {
                    float acc = 0.f;
                    const int t0 = rbeg[sp], t1 = rbeg[sp] + rcnt[sp];
                    for (int t = t0; t < t1; ++t)
                        acc += radial[(long)order[t] * NRAD + j];
                    facc[k][sp] += acc;
                }
            } else if (d == -1) {
#pragma unroll
                for (int sp = 0; sp < NSP; ++sp) {
                    float acc = 0.f;
                    const int t0 = rbeg[sp], t1 = rbeg[sp] + rcnt[sp];
                    for (int t = t0; t < t1; ++t)
                        acc += comp[order[t]];
                    facc[k][sp] += acc;
                }
            }
        }
    }

    // ---- write partials: each (feature, species, a) owned by exactly one thread ----
    float* part = &g_part[a][(size_t)s * NCOLS];
#pragma unroll
    for (int k = 0; k < NSLOTS; ++k) {
        int f = tid + k * NTHREADS;
        if (f >= NFEAT) continue;
#pragma unroll
        for (int sp = 0; sp < NSP; ++sp) {
            int col;
            if (f < NPAIR)             col = NSP + NSP * NRAD + sp * NPAIR + f;
            else if (f < NPAIR + NRAD) col = NSP + sp * NRAD + (f - NPAIR);
            else                       col = sp;
            part[col] = ssc[k] * facc[k][sp];
        }
    }
}

__global__ void reduce_kernel(float* __restrict__ out, int total) {
    int idx = blockIdx.x * blockDim.x + threadIdx.x;
    if (idx >= total) return;
    float v = 0.f;
#pragma unroll
    for (int a = 0; a < ASPLIT; ++a) v += g_part[a][idx];
    out[idx] = v;
}

extern "C" void kernel_launch(void* const* d_in, const int* in_sizes, int n_in,
                              void* d_out, int out_size) {
    const float* comp    = (const float*)d_in[0];
    const float* radial  = (const float*)d_in[1];
    const float* sph0    = (const float*)d_in[2];
    const float* sph1    = (const float*)d_in[3];
    const float* sph2    = (const float*)d_in[4];
    const float* sph3    = (const float*)d_in[5];
    const int*   sidx    = (const int*)d_in[6];
    const int*   species = (const int*)d_in[7];
    float*       out     = (float*)d_out;

    int n_atoms = in_sizes[0];
    int S       = out_size / NCOLS;
    if (S > SMAX) S = SMAX;

    bounds_kernel<<<(n_atoms + 255) / 256, 256>>>(sidx, n_atoms, S);
    dim3 grid(S, ASPLIT);
    le_ace_kernel<<<grid, NTHREADS>>>(comp, radial, sph0, sph1, sph2, sph3,
                                      species, n_atoms, S);
    int total = S * NCOLS;
    reduce_kernel<<<(total + 255) / 256, 256>>>(out, total);
}

// round 6
// speedup vs baseline: 1.0845x; 1.0845x over previous
#include <cuda_runtime.h>

namespace {
constexpr int NTHREADS = 256;
constexpr int ST     = 33;             // smem tile stride (32 atoms + 1 pad)
constexpr int TILE   = 32;
constexpr int NCOEF  = 316;            // 32*1 + 24*3 + 20*5 + 16*7
constexpr int NPAIR  = 1174;           // 528 + 300 + 210 + 136
constexpr int NRAD   = 64;
constexpr int NSP    = 4;
constexpr int NFEAT  = NPAIR + NRAD + 1;   // 1239
constexpr int FSPLIT = 2;
constexpr int HSLOTS = 3;              // slots per split (covers 2*3*256=1536 >= 1239)
constexpr int SMAX   = 256;
constexpr int NCOLS  = NSP * NFEAT;    // 4956
}

__device__ int g_run[SMAX * 5 + 1];    // per structure: run starts for sp=0..3, then end
__device__ int g_order[1 << 16];       // atom indices sorted by (structure, species)

// One block per structure: binary-search bounds in sorted structure_index, then
// deterministically order atoms by species (rank = count of equal species before me).
__global__ void setup_kernel(const int* __restrict__ sidx,
                             const int* __restrict__ species, int n_atoms) {
    const int s   = blockIdx.x;
    const int tid = threadIdx.x;
    __shared__ int cnt[NSP], cnt2[NSP], off[NSP], ssp[NTHREADS];

    // lower_bound(s) and lower_bound(s+1)
    int lo = 0, hi = n_atoms;
    while (lo < hi) { int mid = (lo + hi) >> 1; if (sidx[mid] < s) lo = mid + 1; else hi = mid; }
    const int a0 = lo;
    lo = a0; hi = n_atoms;
    while (lo < hi) { int mid = (lo + hi) >> 1; if (sidx[mid] < s + 1) lo = mid + 1; else hi = mid; }
    const int a1 = lo;

    if (tid < NSP) cnt[tid] = 0;
    __syncthreads();
    for (int chunk = a0; chunk < a1; chunk += NTHREADS) {
        int n = min(NTHREADS, a1 - chunk);
        if (tid < n) atomicAdd(&cnt[species[chunk + tid]], 1);
    }
    __syncthreads();
    if (tid == 0) {
        int p = a0;
#pragma unroll
        for (int sp = 0; sp < NSP; ++sp) { g_run[s * 5 + sp] = p; off[sp] = p; p += cnt[sp]; }
        g_run[s * 5 + 4] = p;
    }
    __syncthreads();
    for (int chunk = a0; chunk < a1; chunk += NTHREADS) {
        int n = min(NTHREADS, a1 - chunk);
        if (tid < NSP) cnt2[tid] = 0;
        if (tid < n) ssp[tid] = species[chunk + tid];
        __syncthreads();
        if (tid < n) {
            int sp = ssp[tid], rank = 0;
            for (int t = 0; t < tid; ++t) rank += (ssp[t] == sp) ? 1 : 0;
            g_order[off[sp] + rank] = chunk + tid;
            atomicAdd(&cnt2[sp], 1);
        }
        __syncthreads();
        if (tid == 0) {
#pragma unroll
            for (int sp = 0; sp < NSP; ++sp) off[sp] += cnt2[sp];
        }
        __syncthreads();
    }
}

// Pair invariant sum over a species run [t0,t1): v = sum_j (-1)^j b1[j]*b2[D-1-j]
template<int D>
__device__ __forceinline__ float run_pairs(const float* __restrict__ b1,
                                           const float* __restrict__ b2,
                                           int t0, int t1) {
    float acc = 0.f;
#pragma unroll 2
    for (int t = t0; t < t1; ++t) {
        float v = b1[t] * b2[(D - 1) * ST + t];
#pragma unroll
        for (int j = 1; j < D; ++j) {
            float x = b1[j * ST + t] * b2[(D - 1 - j) * ST + t];
            v = (j & 1) ? (v - x) : (v + x);
        }
        acc += v;
    }
    return acc;
}

__global__ __launch_bounds__(NTHREADS, 4)
void le_ace_kernel(const float* __restrict__ comp,
                   const float* __restrict__ radial,
                   const float* __restrict__ sph0,
                   const float* __restrict__ sph1,
                   const float* __restrict__ sph2,
                   const float* __restrict__ sph3,
                   float* __restrict__ out,
                   int n_atoms) {
    __shared__ float tileS[NCOEF * ST];     // 41.7 KB
    __shared__ int   sord[TILE];

    const int tid   = threadIdx.x;
    const int lane  = tid & 31;
    const int wid   = tid >> 5;
    const int s     = blockIdx.x;
    const int split = blockIdx.y;

    // ---- per-thread feature-slot metadata (registers only) ----
    // sdv: 1/3/5/7 = pair D; 0 = radial (sc1 = radial col); -1 = comp; -2 = inactive
    int   sc1[HSLOTS], sc2[HSLOTS], sdv[HSLOTS];
    float ssc[HSLOTS];
    float facc[HSLOTS][NSP];
#pragma unroll
    for (int k = 0; k < HSLOTS; ++k) {
        int f = tid + (split * HSLOTS + k) * NTHREADS;
        sc1[k] = 0; sc2[k] = 0; sdv[k] = -2; ssc[k] = 1.f;
#pragma unroll
        for (int sp = 0; sp < NSP; ++sp) facc[k][sp] = 0.f;
        if (f < NPAIR) {
            int l, q, base, coff;
            if (f < 528)       { l = 0; q = 32; base = 0;    coff = 0;   }
            else if (f < 828)  { l = 1; q = 24; base = 528;  coff = 32;  }
            else if (f < 1038) { l = 2; q = 20; base = 828;  coff = 104; }
            else               { l = 3; q = 16; base = 1038; coff = 204; }
            int rem = f - base, i1 = 0;
            while (rem >= q - i1) { rem -= q - i1; ++i1; }   // triangular inversion
            int i2 = i1 + rem;
            int d  = 2 * l + 1;
            sc1[k] = coff + i1 * d;
            sc2[k] = coff + i2 * d;
            sdv[k] = d;
            const float invsq[4] = {1.0f, 0.5773502691896258f,
                                    0.4472135954999579f, 0.3779644730092272f};
            ssc[k] = invsq[l] * ((i1 == i2) ? 1.0f : 1.4142135623730951f);
        } else if (f < NPAIR + NRAD) {
            sdv[k] = 0; sc1[k] = f - NPAIR;
        } else if (f == NPAIR + NRAD) {
            sdv[k] = -1;
        }
    }

    // species run boundaries (absolute positions in g_order)
    int run[5];
#pragma unroll
    for (int r = 0; r < 5; ++r) run[r] = g_run[s * 5 + r];
    const int a0 = run[0];
    const int a1 = run[4];

    for (int base = a0; base < a1; base += TILE) {
        const int nt = min(TILE, a1 - base);
        __syncthreads();                     // previous tile fully consumed
        if (tid < TILE) sord[tid] = (base + tid < a1) ? g_order[base + tid] : -1;
        __syncthreads();
        const int o0 = sord[lane];
        for (int c = wid; c < NCOEF; c += 8) {
            const float* p; int r;
            if (c < 32)       { p = sph0; r = c;       }
            else if (c < 104) { p = sph1; r = c - 32;  }
            else if (c < 204) { p = sph2; r = c - 104; }
            else              { p = sph3; r = c - 204; }
            tileS[c * ST + lane] = (o0 >= 0) ? p[(long)r * n_atoms + o0] : 0.f;
        }
        __syncthreads();

#pragma unroll
        for (int k = 0; k < HSLOTS; ++k) {
            const int d = sdv[k];
            if (d > 0) {
                const float* b1 = tileS + sc1[k] * ST;
                const float* b2 = tileS + sc2[k] * ST;
#pragma unroll
                for (int sp = 0; sp < NSP; ++sp) {
                    const int t0 = max(run[sp] - base, 0);
                    const int t1 = min(run[sp + 1] - base, nt);
                    if (t0 >= t1) continue;
                    float v;
                    switch (d) {
                        case 1:  v = run_pairs<1>(b1, b2, t0, t1); break;
                        case 3:  v = run_pairs<3>(b1, b2, t0, t1); break;
                        case 5:  v = run_pairs<5>(b1, b2, t0, t1); break;
                        default: v = run_pairs<7>(b1, b2, t0, t1); break;
                    }
                    facc[k][sp] += v;
                }
            } else if (d == 0) {
                const int j = sc1[k];
#pragma unroll
                for (int sp = 0; sp < NSP; ++sp) {
                    const int t0 = max(run[sp] - base, 0);
                    const int t1 = min(run[sp + 1] - base, nt);
                    float acc = 0.f;
                    for (int t = t0; t < t1; ++t)
                        acc += radial[(long)sord[t] * NRAD + j];
                    facc[k][sp] += acc;
                }
            } else if (d == -1) {
#pragma unroll
                for (int sp = 0; sp < NSP; ++sp) {
                    const int t0 = max(run[sp] - base, 0);
                    const int t1 = min(run[sp + 1] - base, nt);
                    float acc = 0.f;
                    for (int t = t0; t < t1; ++t)
                        acc += comp[sord[t]];
                    facc[k][sp] += acc;
                }
            }
        }
    }

    // ---- write: each (feature, species) owned by exactly one thread/CTA ----
#pragma unroll
    for (int k = 0; k < HSLOTS; ++k) {
        int f = tid + (split * HSLOTS + k) * NTHREADS;
        if (f >= NFEAT) continue;
#pragma unroll
        for (int sp = 0; sp < NSP; ++sp) {
            int col;
            if (f < NPAIR)             col = NSP + NSP * NRAD + sp * NPAIR + f;  // B2 block
            else if (f < NPAIR + NRAD) col = NSP + sp * NRAD + (f - NPAIR);      // radial block
            else                       col = sp;                                 // composition
            out[s * NCOLS + col] = ssc[k] * facc[k][sp];
        }
    }
}

extern "C" void kernel_launch(void* const* d_in, const int* in_sizes, int n_in,
                              void* d_out, int out_size) {
    const float* comp    = (const float*)d_in[0];
    const float* radial  = (const float*)d_in[1];
    const float* sph0    = (const float*)d_in[2];
    const float* sph1    = (const float*)d_in[3];
    const float* sph2    = (const float*)d_in[4];
    const float* sph3    = (const float*)d_in[5];
    const int*   sidx    = (const int*)d_in[6];
    const int*   species = (const int*)d_in[7];
    float*       out     = (float*)d_out;

    int n_atoms = in_sizes[0];
    int S       = out_size / NCOLS;
    if (S > SMAX) S = SMAX;

    setup_kernel<<<S, NTHREADS>>>(sidx, species, n_atoms);
    dim3 grid(S, FSPLIT);
    le_ace_kernel<<<grid, NTHREADS>>>(comp, radial, sph0, sph1, sph2, sph3,
                                      out, n_atoms);
}